// round 15
// baseline (speedup 1.0000x reference)
#include <cuda_runtime.h>
#include <cuda_fp16.h>
#include <cstdint>

#define N_AG  1024
#define HID   128
#define KDIM  2048
#define OUTD  128
#define CELLS 1024

// ---- scratch (device globals; no allocs allowed) ----
__device__ __align__(16) __half g_Bh[KDIM * HID];    // Wperm hi (fp16)
__device__ __align__(16) __half g_Bls[KDIM * HID];   // Wperm lo * 2^11 (fp16)
__device__ float g_P[N_AG * KDIM];                   // 8 MB projections
__device__ int   g_barrier;                          // inter-CTA barrier (reset by out)

__device__ __forceinline__ uint32_t smem_u32(const void* p) {
    uint32_t a;
    asm("{ .reg .u64 t; cvta.to.shared.u64 t, %1; cvt.u32.u64 %0, t; }" : "=r"(a) : "l"(p));
    return a;
}
__device__ __forceinline__ void griddep_wait() {
    asm volatile("griddepcontrol.wait;" ::: "memory");
}
__device__ __forceinline__ void griddep_launch() {
    asm volatile("griddepcontrol.launch_dependents;" ::: "memory");
}
__device__ __forceinline__ uint32_t ld_acquire_gpu(const int* p) {
    uint32_t v;
    asm volatile("ld.acquire.gpu.b32 %0, [%1];" : "=r"(v) : "l"(p) : "memory");
    return v;
}
__device__ __forceinline__ void ldsm_x4(uint32_t& r0, uint32_t& r1, uint32_t& r2, uint32_t& r3,
                                        uint32_t addr) {
    asm volatile("ldmatrix.sync.aligned.m8n8.x4.shared.b16 {%0,%1,%2,%3}, [%4];"
                 : "=r"(r0), "=r"(r1), "=r"(r2), "=r"(r3) : "r"(addr));
}
__device__ __forceinline__ void mma16816_f16(float* c, const uint32_t* a, const uint32_t* b) {
    asm volatile("mma.sync.aligned.m16n8k16.row.col.f32.f16.f16.f32 "
                 "{%0,%1,%2,%3}, {%4,%5,%6,%7}, {%8,%9}, {%0,%1,%2,%3};"
                 : "+f"(c[0]), "+f"(c[1]), "+f"(c[2]), "+f"(c[3])
                 : "r"(a[0]), "r"(a[1]), "r"(a[2]), "r"(a[3]), "r"(b[0]), "r"(b[1]));
}
__device__ __forceinline__ void cp_async16(uint32_t dst, const void* src) {
    asm volatile("cp.async.cg.shared.global [%0], [%1], 16;" :: "r"(dst), "l"(src) : "memory");
}

// ============== fused prep + mma.sync GEMM (128 co-resident CTAs) ============
// grid (8,16) = 128 CTAs, 1/SM (smem) -> all resident -> spin barrier safe.
// Phase 0: CTA b0 transposes W tile -> g_Bh/g_Bls (fp16 hi / lo*2^11 split).
// Phase 1: A-convert (hidden fp32 -> fp16) into smem while others finish.
// Phase 2: spin on g_barrier==128, cp.async B tiles (L2, fenced), 2-pass MMA.
#define LDS   136
#define TILE  (128 * LDS)
#define SMEM_DYN (3 * TILE * 2)            // 104448 B

__global__ void __launch_bounds__(256, 1) gemm_mma_kernel(const float* __restrict__ Hs,
                                                          const float* __restrict__ W) {
    extern __shared__ __half sm[];
    __half* sAh = sm;
    __half* sBh = sm + TILE;
    __half* sBl = sm + 2 * TILE;
    float*  cwf = (float*)sm;              // [8][257] staging, aliases sAh region

    const int t  = threadIdx.x;
    const int w  = t >> 5;
    const int l  = t & 31;
    const int m0 = blockIdx.x << 7;
    const int n0 = blockIdx.y << 7;
    const int wm = (w >> 2) * 64;
    const int wn = (w & 3) * 32;

    griddep_launch();                      // out_kernel may start its scatter now

    // ---- Phase 0: this CTA's W tile -> Wperm fp16 split in global ----
    {
        const int b0 = blockIdx.x * 16 + blockIdx.y;   // 0..127
        const int nt = b0 >> 3, kt = b0 & 7;
        const int n0p = nt * 8, k0p = kt * 256, h0p = kt * 16;
#pragma unroll
        for (int q = t; q < 512; q += 256) {           // 8x256 fp32 tile
            int r = q >> 6, c4 = q & 63;
            float4 v = *(const float4*)(W + (n0p + r) * KDIM + k0p + c4 * 4);
            cwf[r * 257 + c4 * 4 + 0] = v.x;           // 257-stride: no STS.128
            cwf[r * 257 + c4 * 4 + 1] = v.y;
            cwf[r * 257 + c4 * 4 + 2] = v.z;
            cwf[r * 257 + c4 * 4 + 3] = v.w;
        }
        __syncthreads();
        if (t < 128) {                                 // 128 (blk,nn) rows
            const int blk = t >> 3, nn = t & 7;
            const int rr = (blk << 7) | (n0p + nn);
            __align__(16) __half hi[16];
            __align__(16) __half lo[16];
#pragma unroll
            for (int hr = 0; hr < 16; hr++) {
                float v = cwf[nn * 257 + hr * 16 + blk];
                hi[hr] = __float2half_rn(v);
                lo[hr] = __float2half_rn((v - __half2float(hi[hr])) * 2048.0f);
            }
            *(uint4*)(g_Bh  + rr * HID + h0p)     = *(const uint4*)&hi[0];
            *(uint4*)(g_Bh  + rr * HID + h0p + 8) = *(const uint4*)&hi[8];
            *(uint4*)(g_Bls + rr * HID + h0p)     = *(const uint4*)&lo[0];
            *(uint4*)(g_Bls + rr * HID + h0p + 8) = *(const uint4*)&lo[8];
        }
        __threadfence();                               // writes -> GPU scope (L2)
        __syncthreads();
        if (t == 0) atomicAdd(&g_barrier, 1);
    }

    // ---- Phase 1: A convert (independent; hides barrier skew) ----
#pragma unroll
    for (int q = t; q < 4096; q += 256) {  // 128 rows x 32 float4
        int r = q >> 5, c = q & 31;
        float4 v = *(const float4*)(Hs + (m0 + r) * HID + c * 4);
        __align__(8) __half hi[4];
        hi[0] = __float2half_rn(v.x);
        hi[1] = __float2half_rn(v.y);
        hi[2] = __float2half_rn(v.z);
        hi[3] = __float2half_rn(v.w);
        *(uint2*)(sAh + r * LDS + c * 4) = *(const uint2*)&hi[0];
    }

    // ---- Phase 2: wait for all 128 prep tiles ----
    if (t == 0) {
        while (ld_acquire_gpu(&g_barrier) < 128) __nanosleep(64);
    }
    __syncthreads();

    // ---- B tiles (cp.async.cg reads L2 -> sees fenced prep writes) ----
#pragma unroll
    for (int q = t; q < 2048; q += 256) {  // 16B chunks
        int r = q >> 4, c = q & 15;
        cp_async16(smem_u32(sBh + r * LDS + c * 8), g_Bh  + (n0 + r) * HID + c * 8);
        cp_async16(smem_u32(sBl + r * LDS + c * 8), g_Bls + (n0 + r) * HID + c * 8);
    }
    asm volatile("cp.async.commit_group;" ::: "memory");
    asm volatile("cp.async.wait_group 0;" ::: "memory");
    __syncthreads();

    float acc[4][4][4], accLo[4][4][4];
#pragma unroll
    for (int mi = 0; mi < 4; mi++)
#pragma unroll
        for (int ni = 0; ni < 4; ni++)
#pragma unroll
            for (int q = 0; q < 4; q++) { acc[mi][ni][q] = 0.0f; accLo[mi][ni][q] = 0.0f; }

    const int aRow = wm + (l & 15);
    const int aCol = (l >> 4) * 8;
    const int bRow = wn + ((l >> 4) * 8) + (l & 7);
    const int bCol = ((l >> 3) & 1) * 8;

    const uint32_t aHB = smem_u32(sAh + aRow * LDS + aCol);
    const uint32_t bHB = smem_u32(sBh + bRow * LDS + bCol);
    const uint32_t bLB = smem_u32(sBl + bRow * LDS + bCol);

#pragma unroll
    for (int kk = 0; kk < 8; kk++) {
        const uint32_t ko = kk * 32;       // kk*16 elements * 2B
        uint32_t aH[4][4], bH[4][2], bL[4][2];
#pragma unroll
        for (int mi = 0; mi < 4; mi++)
            ldsm_x4(aH[mi][0], aH[mi][1], aH[mi][2], aH[mi][3],
                    aHB + mi * (16 * LDS * 2) + ko);
#pragma unroll
        for (int bi = 0; bi < 2; bi++) {
            ldsm_x4(bH[2 * bi][0], bH[2 * bi][1], bH[2 * bi + 1][0], bH[2 * bi + 1][1],
                    bHB + bi * (16 * LDS * 2) + ko);
            ldsm_x4(bL[2 * bi][0], bL[2 * bi][1], bL[2 * bi + 1][0], bL[2 * bi + 1][1],
                    bLB + bi * (16 * LDS * 2) + ko);
        }
#pragma unroll
        for (int mi = 0; mi < 4; mi++)
#pragma unroll
            for (int ni = 0; ni < 4; ni++) {
                mma16816_f16(acc[mi][ni],   aH[mi], bH[ni]);
                mma16816_f16(accLo[mi][ni], aH[mi], bL[ni]);
            }
    }

    const float s = 1.0f / 2048.0f;
    const int g2 = l >> 2, tig = l & 3;
#pragma unroll
    for (int mi = 0; mi < 4; mi++) {
        const int row = m0 + wm + mi * 16 + g2;
#pragma unroll
        for (int ni = 0; ni < 4; ni++) {
            const int col = n0 + wn + ni * 8 + tig * 2;
            *(float2*)(g_P + row * KDIM + col) =
                make_float2(acc[mi][ni][0] + accLo[mi][ni][0] * s,
                            acc[mi][ni][1] + accLo[mi][ni][1] * s);
            *(float2*)(g_P + (row + 8) * KDIM + col) =
                make_float2(acc[mi][ni][2] + accLo[mi][ni][2] * s,
                            acc[mi][ni][3] + accLo[mi][ni][3] * s);
        }
    }
}

// ================= fused scatter + output gather =============================
// One CTA per ego. Scatter (obs2 only, overlaps GEMM via PDL early-launch),
// then griddepcontrol.wait (gemm complete), then gather P rows.
__global__ void __launch_bounds__(256) out_kernel(const float* __restrict__ obs2,
                                                  const float* __restrict__ b,
                                                  float* __restrict__ out) {
    __shared__ int    w[CELLS];
    __shared__ int    se[CELLS];
    __shared__ int    s_cnt;
    __shared__ float4 sp[8][32];
    const int i = blockIdx.x;
    const int t = threadIdx.x;     // 256
    const int g = t >> 5, l = t & 31;

    for (int c = t; c < CELLS; c += 256) w[c] = -1;
    if (t == 0) s_cnt = 0;
    const float2 oi = ((const float2*)obs2)[i];    // broadcast load
    __syncthreads();

    int cnt = 0;
    if (oi.x == oi.x) {                            // ego not NaN (uniform)
        for (int j = t; j < N_AG; j += 256) {      // obs2 L2-resident (8KB)
            if (j == i) continue;
            float2 oj = ((const float2*)obs2)[j];
            if (oj.x != oj.x) continue;            // neighbor NaN
            float ox = (oj.x - oi.x) * 4.0f + 16.0f;   // exact pow2 scale
            float oy = (oj.y - oi.y) * 4.0f + 16.0f;
            if (ox >= 0.0f && ox < 32.0f && oy >= 0.0f && oy < 32.0f)
                atomicMax(&w[((int)ox) * 32 + (int)oy], j);  // set-sem: max j
        }
        __syncthreads();
        for (int c = t; c < CELLS; c += 256) {
            int j = w[c];
            if (j >= 0) {
                int blk = ((c >> 8) << 2) | ((c & 31) >> 3);   // gi*4+gj
                int p = atomicAdd(&s_cnt, 1);
                se[p] = (j << 11) | (blk << 7);    // row offset into P
            }
        }
        __syncthreads();
        cnt = s_cnt;
    }

    griddep_wait();                                // gemm complete -> g_P visible
    if (i == 0 && t == 0) g_barrier = 0;           // reset for next replay

    float4 acc = make_float4(0.f, 0.f, 0.f, 0.f);
    for (int e = g; e < cnt; e += 8) {
        float4 v = *(const float4*)(g_P + se[e] + l * 4);
        acc.x += v.x; acc.y += v.y; acc.z += v.z; acc.w += v.w;
    }
    sp[g][l] = acc;
    __syncthreads();

    if (g == 0) {
        float4 s = sp[0][l];
#pragma unroll
        for (int q = 1; q < 8; q++) {
            float4 v = sp[q][l];
            s.x += v.x; s.y += v.y; s.z += v.z; s.w += v.w;
        }
        float4 bv = ((const float4*)b)[l];
        s.x = fmaxf(s.x + bv.x, 0.f);
        s.y = fmaxf(s.y + bv.y, 0.f);
        s.z = fmaxf(s.z + bv.z, 0.f);
        s.w = fmaxf(s.w + bv.w, 0.f);
        ((float4*)(out + i * OUTD))[l] = s;
    }
}

// =============================================================================
extern "C" void kernel_launch(void* const* d_in, const int* in_sizes, int n_in,
                              void* d_out, int out_size) {
    const float* hidden = (const float*)d_in[0];
    const float* obs2   = (const float*)d_in[2];
    const float* W      = (const float*)d_in[3];
    const float* b      = (const float*)d_in[4];
    float*       out    = (float*)d_out;

    cudaFuncSetAttribute(gemm_mma_kernel, cudaFuncAttributeMaxDynamicSharedMemorySize, SMEM_DYN);

    dim3 ggrid(N_AG / 128, KDIM / 128);   // (8, 16) = 128 CTAs, all co-resident
    gemm_mma_kernel<<<ggrid, 256, SMEM_DYN>>>(hidden, W);

    cudaLaunchAttribute attr[1];
    attr[0].id = cudaLaunchAttributeProgrammaticStreamSerialization;
    attr[0].val.programmaticStreamSerializationAllowed = 1;

    cudaLaunchConfig_t cfg = {};
    cfg.gridDim = dim3(N_AG);
    cfg.blockDim = dim3(256);
    cfg.dynamicSmemBytes = 0;
    cfg.stream = 0;
    cfg.attrs = attr;
    cfg.numAttrs = 1;
    cudaLaunchKernelEx(&cfg, out_kernel, obs2, b, out);
}